// round 4
// baseline (speedup 1.0000x reference)
#include <cuda_runtime.h>
#include <cuda_bf16.h>

#define N_NODES 65536
#define N_EDGES 1048576
#define IN_F    64
#define OUT_F   64

// -------- device-global scratch (allocation-free) --------
__device__ float g_support[(size_t)N_NODES * OUT_F];   // 16 MB, X @ W
__device__ int   g_cnt[N_NODES];                       // per-row edge counts
__device__ int   g_rowptr[N_NODES + 1];                // CSR row pointers
__device__ int   g_cursor[N_NODES];                    // scatter cursors
__device__ int   g_ecol[N_EDGES];                      // CSR col indices
__device__ float g_eval[N_EDGES];                      // CSR edge values

// ---------------------------------------------------------
// Kernel 1: support = X @ W   (tiled, W + X-tile in shared)
// block = 256 threads, 32 rows per block, 8 threads/row, 8 outputs/thread
// ---------------------------------------------------------
__global__ void __launch_bounds__(256) gemm_kernel(const float* __restrict__ X,
                                                   const float* __restrict__ W)
{
    __shared__ float sW[IN_F * OUT_F];   // 16 KB
    __shared__ float sX[32 * IN_F];      // 8 KB

    const int tid = threadIdx.x;
    const int rowBase = blockIdx.x * 32;

    // load W (4096 floats = 1024 float4)
    for (int i = tid; i < IN_F * OUT_F / 4; i += 256)
        ((float4*)sW)[i] = ((const float4*)W)[i];
    // load X tile (2048 floats = 512 float4)
    for (int i = tid; i < 32 * IN_F / 4; i += 256)
        ((float4*)sX)[i] = ((const float4*)(X + (size_t)rowBase * IN_F))[i];
    __syncthreads();

    const int r   = tid >> 3;        // 0..31  local row
    const int sub = tid & 7;         // 0..7   output group (8 cols)

    float acc[8];
#pragma unroll
    for (int j = 0; j < 8; j++) acc[j] = 0.f;

#pragma unroll 8
    for (int k = 0; k < IN_F; k++) {
        const float xv = sX[r * IN_F + k];
#pragma unroll
        for (int j = 0; j < 8; j++)
            acc[j] += xv * sW[k * OUT_F + 8 * sub + j];
    }

    float* out = g_support + ((size_t)(rowBase + r) * OUT_F + 8 * sub);
    float4 o0 = {acc[0], acc[1], acc[2], acc[3]};
    float4 o1 = {acc[4], acc[5], acc[6], acc[7]};
    *(float4*)(out)     = o0;
    *(float4*)(out + 4) = o1;
}

// ---------------------------------------------------------
// Kernel 2: zero the histogram counters
// ---------------------------------------------------------
__global__ void zero_cnt_kernel()
{
    int i = blockIdx.x * blockDim.x + threadIdx.x;
    if (i < N_NODES) g_cnt[i] = 0;
}

// ---------------------------------------------------------
// Kernel 3: histogram of destination rows
// ---------------------------------------------------------
__global__ void hist_kernel(const int* __restrict__ rows)
{
    int e = blockIdx.x * blockDim.x + threadIdx.x;
    if (e < N_EDGES) atomicAdd(&g_cnt[rows[e]], 1);
}

// ---------------------------------------------------------
// Kernel 4: exclusive scan of 65536 counts (single block, 1024 threads,
// 64 elements/thread, Hillis-Steele over per-thread sums). Writes rowptr
// and initializes the scatter cursors.
// ---------------------------------------------------------
__global__ void __launch_bounds__(1024) scan_kernel()
{
    __shared__ int ssum[1024];
    const int t    = threadIdx.x;
    const int base = t * 64;

    // pass 1: per-thread chunk total
    int s = 0;
#pragma unroll 4
    for (int i = 0; i < 64; i++) s += g_cnt[base + i];
    ssum[t] = s;
    __syncthreads();

    // inclusive scan of per-thread totals
    for (int off = 1; off < 1024; off <<= 1) {
        int v = (t >= off) ? ssum[t - off] : 0;
        __syncthreads();
        ssum[t] += v;
        __syncthreads();
    }

    // pass 2: re-read counts, emit exclusive prefix
    int p = (t == 0) ? 0 : ssum[t - 1];
#pragma unroll 4
    for (int i = 0; i < 64; i++) {
        g_rowptr[base + i] = p;
        g_cursor[base + i] = p;
        p += g_cnt[base + i];
    }
    if (t == 1023) g_rowptr[N_NODES] = ssum[1023];
}

// ---------------------------------------------------------
// Kernel 5: scatter COO edges into CSR order
// ---------------------------------------------------------
__global__ void scatter_kernel(const int*   __restrict__ rows,
                               const int*   __restrict__ cols,
                               const float* __restrict__ vals)
{
    int e = blockIdx.x * blockDim.x + threadIdx.x;
    if (e < N_EDGES) {
        int p = atomicAdd(&g_cursor[rows[e]], 1);
        g_ecol[p] = cols[e];
        g_eval[p] = vals[e];
    }
}

// ---------------------------------------------------------
// Kernel 6: CSR SpMM + bias + ReLU
// one warp per output row; lanes 0-15 handle even edges, 16-31 odd edges;
// each lane owns 4 features (float4 gather = coalesced 256B per edge).
// ---------------------------------------------------------
__global__ void __launch_bounds__(256) spmm_kernel(const float* __restrict__ bias,
                                                   float*       __restrict__ out)
{
    const int warp = (blockIdx.x * blockDim.x + threadIdx.x) >> 5;
    const int lane = threadIdx.x & 31;
    if (warp >= N_NODES) return;

    const int beg = g_rowptr[warp];
    const int end = g_rowptr[warp + 1];

    const int half = lane >> 4;         // 0: even edges, 1: odd edges
    const int fl   = (lane & 15) * 4;   // feature offset of this lane

    float4 acc = {0.f, 0.f, 0.f, 0.f};

    for (int i = beg + half; i < end; i += 2) {
        const int   col = g_ecol[i];
        const float v   = g_eval[i];
        const float4 sv = *(const float4*)(g_support + (size_t)col * OUT_F + fl);
        acc.x += v * sv.x;
        acc.y += v * sv.y;
        acc.z += v * sv.z;
        acc.w += v * sv.w;
    }

    // combine even/odd halves
    acc.x += __shfl_xor_sync(0xffffffff, acc.x, 16);
    acc.y += __shfl_xor_sync(0xffffffff, acc.y, 16);
    acc.z += __shfl_xor_sync(0xffffffff, acc.z, 16);
    acc.w += __shfl_xor_sync(0xffffffff, acc.w, 16);

    if (half == 0) {
        const float4 b = *(const float4*)(bias + fl);
        float4 o;
        o.x = fmaxf(acc.x + b.x, 0.f);
        o.y = fmaxf(acc.y + b.y, 0.f);
        o.z = fmaxf(acc.z + b.z, 0.f);
        o.w = fmaxf(acc.w + b.w, 0.f);
        *(float4*)(out + (size_t)warp * OUT_F + fl) = o;
    }
}

// ---------------------------------------------------------
// launch
// ---------------------------------------------------------
extern "C" void kernel_launch(void* const* d_in, const int* in_sizes, int n_in,
                              void* d_out, int out_size)
{
    const float* X     = (const float*)d_in[0];   // [N_NODES, IN_F]
    const int*   erow  = (const int*)  d_in[1];   // [N_EDGES]
    const int*   ecol  = (const int*)  d_in[2];   // [N_EDGES]
    const float* eval  = (const float*)d_in[3];   // [N_EDGES]
    const float* W     = (const float*)d_in[4];   // [IN_F, OUT_F]
    const float* bias  = (const float*)d_in[5];   // [OUT_F]
    float*       out   = (float*)d_out;           // [N_NODES, OUT_F]

    // 1) support = X @ W
    gemm_kernel<<<N_NODES / 32, 256>>>(X, W);

    // 2-5) build CSR
    zero_cnt_kernel<<<N_NODES / 256, 256>>>();
    hist_kernel<<<N_EDGES / 256, 256>>>(erow);
    scan_kernel<<<1, 1024>>>();
    scatter_kernel<<<N_EDGES / 256, 256>>>(erow, ecol, eval);

    // 6) SpMM + bias + ReLU  (one warp per row, 8 warps per block)
    spmm_kernel<<<N_NODES / 8, 256>>>(bias, out);
}

// round 5
// speedup vs baseline: 2.3525x; 2.3525x over previous
#include <cuda_runtime.h>
#include <cuda_bf16.h>

#define N_NODES 65536
#define N_EDGES 1048576
#define IN_F    64
#define OUT_F   64

#define SCAN_BLOCKS 256
#define SCAN_CHUNK  256   // N_NODES / SCAN_BLOCKS

// -------- device-global scratch (allocation-free) --------
__device__ float g_support[(size_t)N_NODES * OUT_F];   // 16 MB, X @ W
__device__ int   g_cnt[N_NODES];                       // per-row edge counts
__device__ int   g_rowptr[N_NODES + 1];                // CSR row pointers
__device__ int   g_cursor[N_NODES];                    // scatter cursors
__device__ int   g_ecol[N_EDGES];                      // CSR col indices
__device__ float g_eval[N_EDGES];                      // CSR edge values
__device__ int   g_bsum[SCAN_BLOCKS];                  // per-block sums
__device__ int   g_boff[SCAN_BLOCKS];                  // per-block offsets

// ---------------------------------------------------------
// Kernel 1: support = X @ W   (tiled, W + X-tile in shared)
// ---------------------------------------------------------
__global__ void __launch_bounds__(256) gemm_kernel(const float* __restrict__ X,
                                                   const float* __restrict__ W)
{
    __shared__ float sW[IN_F * OUT_F];   // 16 KB
    __shared__ float sX[32 * IN_F];      // 8 KB

    const int tid = threadIdx.x;
    const int rowBase = blockIdx.x * 32;

    for (int i = tid; i < IN_F * OUT_F / 4; i += 256)
        ((float4*)sW)[i] = ((const float4*)W)[i];
    for (int i = tid; i < 32 * IN_F / 4; i += 256)
        ((float4*)sX)[i] = ((const float4*)(X + (size_t)rowBase * IN_F))[i];
    __syncthreads();

    const int r   = tid >> 3;
    const int sub = tid & 7;

    float acc[8];
#pragma unroll
    for (int j = 0; j < 8; j++) acc[j] = 0.f;

#pragma unroll 8
    for (int k = 0; k < IN_F; k++) {
        const float xv = sX[r * IN_F + k];
#pragma unroll
        for (int j = 0; j < 8; j++)
            acc[j] += xv * sW[k * OUT_F + 8 * sub + j];
    }

    float* out = g_support + ((size_t)(rowBase + r) * OUT_F + 8 * sub);
    float4 o0 = {acc[0], acc[1], acc[2], acc[3]};
    float4 o1 = {acc[4], acc[5], acc[6], acc[7]};
    *(float4*)(out)     = o0;
    *(float4*)(out + 4) = o1;
}

// ---------------------------------------------------------
// Kernel 2: zero histogram counters
// ---------------------------------------------------------
__global__ void zero_cnt_kernel()
{
    int i = blockIdx.x * blockDim.x + threadIdx.x;
    if (i < N_NODES) g_cnt[i] = 0;
}

// ---------------------------------------------------------
// Kernel 3: histogram of destination rows
// ---------------------------------------------------------
__global__ void hist_kernel(const int* __restrict__ rows)
{
    int e = blockIdx.x * blockDim.x + threadIdx.x;
    if (e < N_EDGES) atomicAdd(&g_cnt[rows[e]], 1);
}

// ---------------------------------------------------------
// Kernel 4a: per-block reduction of counts (256 blocks x 256 counts)
// ---------------------------------------------------------
__global__ void __launch_bounds__(256) block_reduce_kernel()
{
    __shared__ int sh[8];
    const int t = threadIdx.x;
    int v = g_cnt[blockIdx.x * SCAN_CHUNK + t];

    // warp reduce
#pragma unroll
    for (int off = 16; off > 0; off >>= 1)
        v += __shfl_down_sync(0xffffffff, v, off);
    if ((t & 31) == 0) sh[t >> 5] = v;
    __syncthreads();
    if (t < 8) {
        int s = sh[t];
#pragma unroll
        for (int off = 4; off > 0; off >>= 1)
            s += __shfl_down_sync(0xff, s, off);
        if (t == 0) g_bsum[blockIdx.x] = s;
    }
}

// ---------------------------------------------------------
// Kernel 4b: exclusive scan of the 256 block sums (1 block)
// ---------------------------------------------------------
__global__ void __launch_bounds__(256) scan_bsum_kernel()
{
    __shared__ int sh[256];
    const int t = threadIdx.x;
    int v = g_bsum[t];
    sh[t] = v;
    __syncthreads();
#pragma unroll
    for (int off = 1; off < 256; off <<= 1) {
        int u = (t >= off) ? sh[t - off] : 0;
        __syncthreads();
        sh[t] += u;
        __syncthreads();
    }
    g_boff[t] = sh[t] - v;                       // exclusive
    if (t == 255) g_rowptr[N_NODES] = sh[255];   // grand total
}

// ---------------------------------------------------------
// Kernel 4c: per-block exclusive scan + offset -> rowptr, cursor
// ---------------------------------------------------------
__global__ void __launch_bounds__(256) block_scan_kernel()
{
    __shared__ int sh[256];
    const int t = threadIdx.x;
    const int gi = blockIdx.x * SCAN_CHUNK + t;
    const int v = g_cnt[gi];
    sh[t] = v;
    __syncthreads();
#pragma unroll
    for (int off = 1; off < 256; off <<= 1) {
        int u = (t >= off) ? sh[t - off] : 0;
        __syncthreads();
        sh[t] += u;
        __syncthreads();
    }
    const int p = g_boff[blockIdx.x] + sh[t] - v;  // exclusive prefix
    g_rowptr[gi] = p;
    g_cursor[gi] = p;
}

// ---------------------------------------------------------
// Kernel 5: scatter COO edges into CSR order
// ---------------------------------------------------------
__global__ void scatter_kernel(const int*   __restrict__ rows,
                               const int*   __restrict__ cols,
                               const float* __restrict__ vals)
{
    int e = blockIdx.x * blockDim.x + threadIdx.x;
    if (e < N_EDGES) {
        int p = atomicAdd(&g_cursor[rows[e]], 1);
        g_ecol[p] = cols[e];
        g_eval[p] = vals[e];
    }
}

// ---------------------------------------------------------
// Kernel 6: CSR SpMM + bias + ReLU
// one warp per row; lanes 0-15 even edges, 16-31 odd edges; float4 gathers.
// ---------------------------------------------------------
__global__ void __launch_bounds__(256) spmm_kernel(const float* __restrict__ bias,
                                                   float*       __restrict__ out)
{
    const int warp = (blockIdx.x * blockDim.x + threadIdx.x) >> 5;
    const int lane = threadIdx.x & 31;
    if (warp >= N_NODES) return;

    const int beg = g_rowptr[warp];
    const int end = g_rowptr[warp + 1];

    const int half = lane >> 4;
    const int fl   = (lane & 15) * 4;

    float4 acc = {0.f, 0.f, 0.f, 0.f};

    for (int i = beg + half; i < end; i += 2) {
        const int   col = g_ecol[i];
        const float v   = g_eval[i];
        const float4 sv = *(const float4*)(g_support + (size_t)col * OUT_F + fl);
        acc.x += v * sv.x;
        acc.y += v * sv.y;
        acc.z += v * sv.z;
        acc.w += v * sv.w;
    }

    acc.x += __shfl_xor_sync(0xffffffff, acc.x, 16);
    acc.y += __shfl_xor_sync(0xffffffff, acc.y, 16);
    acc.z += __shfl_xor_sync(0xffffffff, acc.z, 16);
    acc.w += __shfl_xor_sync(0xffffffff, acc.w, 16);

    if (half == 0) {
        const float4 b = *(const float4*)(bias + fl);
        float4 o;
        o.x = fmaxf(acc.x + b.x, 0.f);
        o.y = fmaxf(acc.y + b.y, 0.f);
        o.z = fmaxf(acc.z + b.z, 0.f);
        o.w = fmaxf(acc.w + b.w, 0.f);
        *(float4*)(out + (size_t)warp * OUT_F + fl) = o;
    }
}

// ---------------------------------------------------------
// launch
// ---------------------------------------------------------
extern "C" void kernel_launch(void* const* d_in, const int* in_sizes, int n_in,
                              void* d_out, int out_size)
{
    const float* X     = (const float*)d_in[0];
    const int*   erow  = (const int*)  d_in[1];
    const int*   ecol  = (const int*)  d_in[2];
    const float* eval  = (const float*)d_in[3];
    const float* W     = (const float*)d_in[4];
    const float* bias  = (const float*)d_in[5];
    float*       out   = (float*)d_out;

    gemm_kernel<<<N_NODES / 32, 256>>>(X, W);

    zero_cnt_kernel<<<N_NODES / 256, 256>>>();
    hist_kernel<<<N_EDGES / 256, 256>>>(erow);

    block_reduce_kernel<<<SCAN_BLOCKS, 256>>>();
    scan_bsum_kernel<<<1, 256>>>();
    block_scan_kernel<<<SCAN_BLOCKS, 256>>>();

    scatter_kernel<<<N_EDGES / 256, 256>>>(erow, ecol, eval);

    spmm_kernel<<<N_NODES / 8, 256>>>(bias, out);
}